// round 1
// baseline (speedup 1.0000x reference)
#include <cuda_runtime.h>
#include <cuda_bf16.h>
#include <math.h>
#include <limits.h>

#define N_NODES 100000
#define N_EDGES 1600000
#define NFEAT 128
#define NHID 32
#define NCLASS 40
#define NEG_SLOPE 0.2f

// ---------------- scratch (device globals; no allocation allowed) ----------
__device__ float g_h1[N_NODES * NHID];     // layer1 pre-activation node features
__device__ float g_acc1[N_NODES * NHID];   // layer1 unnormalized message accum
__device__ float g_x2[N_NODES * NHID];     // layer1 output (input to layer2)
__device__ float g_h2[N_NODES * NCLASS];   // layer2 node features
__device__ float g_acc2[N_NODES * NCLASS]; // layer2 unnormalized message accum
__device__ float g_asrc[N_NODES];
__device__ float g_adst[N_NODES];
__device__ float g_denom[N_NODES];
__device__ int   g_mord[N_NODES];          // ordered-int encoded segment max

// ---------------- helpers ---------------------------------------------------
__device__ __forceinline__ int f2ord(float f) {
    int i = __float_as_int(f);
    return i >= 0 ? i : (i ^ 0x7FFFFFFF);
}
__device__ __forceinline__ float ord2f(int i) {
    return __int_as_float(i >= 0 ? i : (i ^ 0x7FFFFFFF));
}
__device__ __forceinline__ float lrelu(float x) {
    return x > 0.f ? x : NEG_SLOPE * x;
}

// ---------------- init ------------------------------------------------------
__global__ void init_kernel(int accN, int layer) {
    int i = blockIdx.x * blockDim.x + threadIdx.x;
    if (i < accN) {
        if (layer == 0) g_acc1[i] = 0.f;
        else            g_acc2[i] = 0.f;
    }
    if (i < N_NODES) {
        g_denom[i] = 0.f;
        g_mord[i]  = INT_MIN;
    }
}

// ---------------- layer 1 GEMM: h1 = x @ W1, + alpha_src/dst ---------------
// 256 threads, 32 nodes per block. W1 (16KB) + x tile (16KB) in smem.
__global__ void gemm1_kernel(const float* __restrict__ x,
                             const float* __restrict__ W1,
                             const float* __restrict__ a_src,
                             const float* __restrict__ a_dst) {
    __shared__ float Wsh[NFEAT * NHID];
    __shared__ float xsh[32][NFEAT];
    __shared__ float as[NHID], ad[NHID];
    int tid = threadIdx.x;
    int base = blockIdx.x * 32;

    for (int i = tid; i < NFEAT * NHID; i += 256) Wsh[i] = W1[i];
    if (tid < NHID) { as[tid] = a_src[tid]; ad[tid] = a_dst[tid]; }
    for (int i = tid; i < 32 * NFEAT; i += 256) {
        int r = i >> 7, cc = i & 127;
        xsh[r][cc] = x[(size_t)(base + r) * NFEAT + cc];
    }
    __syncthreads();

    int c = tid & 31, rr = tid >> 5;  // channel, node sub-row
    float acc[4] = {0.f, 0.f, 0.f, 0.f};
    #pragma unroll 8
    for (int k = 0; k < NFEAT; k++) {
        float wk = Wsh[k * NHID + c];
        acc[0] += xsh[rr     ][k] * wk;
        acc[1] += xsh[rr +  8][k] * wk;
        acc[2] += xsh[rr + 16][k] * wk;
        acc[3] += xsh[rr + 24][k] * wk;
    }
    #pragma unroll
    for (int j = 0; j < 4; j++) {
        int n = base + rr + 8 * j;
        g_h1[n * NHID + c] = acc[j];
        float av = acc[j] * as[c];
        float dv = acc[j] * ad[c];
        #pragma unroll
        for (int o = 16; o > 0; o >>= 1) {
            av += __shfl_xor_sync(0xffffffffu, av, o);
            dv += __shfl_xor_sync(0xffffffffu, dv, o);
        }
        if (c == 0) { g_asrc[n] = av; g_adst[n] = dv; }
    }
}

// ---------------- layer 2 GEMM: h2 = x2 @ W2 (warp per node, shfl) ---------
__global__ void gemm2_kernel(const float* __restrict__ W2,
                             const float* __restrict__ a_src,
                             const float* __restrict__ a_dst) {
    __shared__ float Wsh[NHID * NCLASS];
    __shared__ float as[NCLASS], ad[NCLASS];
    int tid = threadIdx.x;
    for (int i = tid; i < NHID * NCLASS; i += 256) Wsh[i] = W2[i];
    if (tid < NCLASS) { as[tid] = a_src[tid]; ad[tid] = a_dst[tid]; }
    __syncthreads();

    int lane = tid & 31, w = tid >> 5;
    int n = blockIdx.x * 8 + w;
    float hval = g_x2[n * NHID + lane];
    bool act1 = lane < 8;
    int c0 = lane;
    int c1 = act1 ? lane + 32 : 0;
    float acc0 = 0.f, acc1 = 0.f;
    #pragma unroll
    for (int k = 0; k < NHID; k++) {
        float hk = __shfl_sync(0xffffffffu, hval, k);
        acc0 += hk * Wsh[k * NCLASS + c0];
        acc1 += hk * Wsh[k * NCLASS + c1];
    }
    g_h2[n * NCLASS + c0] = acc0;
    if (act1) g_h2[n * NCLASS + 32 + lane] = acc1;

    float av = acc0 * as[c0] + (act1 ? acc1 * as[c1] : 0.f);
    float dv = acc0 * ad[c0] + (act1 ? acc1 * ad[c1] : 0.f);
    #pragma unroll
    for (int o = 16; o > 0; o >>= 1) {
        av += __shfl_xor_sync(0xffffffffu, av, o);
        dv += __shfl_xor_sync(0xffffffffu, dv, o);
    }
    if (lane == 0) { g_asrc[n] = av; g_adst[n] = dv; }
}

// ---------------- edge pass 1: segment max via ordered-int atomicMax -------
__global__ void edge_max_kernel(const int* __restrict__ src,
                                const int* __restrict__ dst) {
    int e = blockIdx.x * blockDim.x + threadIdx.x;
    if (e >= N_EDGES) return;
    int s = src[e], d = dst[e];
    float sc = lrelu(g_asrc[s] + g_adst[d]);
    atomicMax(&g_mord[d], f2ord(sc));
}

// ---------------- edge pass 2: fused exp + denom + weighted scatter --------
// One warp per edge. Accumulates UNNORMALIZED numerator; divide in finalize.
template <int C>
__global__ void edge_accum_kernel(const int* __restrict__ src,
                                  const int* __restrict__ dst) {
    int idx = blockIdx.x * blockDim.x + threadIdx.x;
    int e = idx >> 5, lane = idx & 31;
    if (e >= N_EDGES) return;
    const float* __restrict__ h  = (C == NHID) ? g_h1  : g_h2;
    float* __restrict__       ac = (C == NHID) ? g_acc1 : g_acc2;
    int s = src[e], d = dst[e];
    float sc = lrelu(g_asrc[s] + g_adst[d]);
    float mm = ord2f(g_mord[d]);
    float ee = __expf(sc - mm);
    if (lane == 0) atomicAdd(&g_denom[d], ee);
    #pragma unroll
    for (int c = lane; c < C; c += 32)
        atomicAdd(&ac[d * C + c], ee * h[s * C + c]);
}

// ---------------- finalize layer 1: normalize + bias + relu ----------------
__global__ void finalize1_kernel(const float* __restrict__ b1) {
    int i = blockIdx.x * blockDim.x + threadIdx.x;
    if (i >= N_NODES * NHID) return;
    int n = i >> 5, c = i & 31;
    float v = g_acc1[i] / (g_denom[n] + 1e-16f) + b1[c];
    g_x2[i] = v > 0.f ? v : 0.f;
}

// ---------------- finalize layer 2: normalize + bias + log_softmax ---------
__global__ void finalize2_kernel(const float* __restrict__ b2,
                                 float* __restrict__ out) {
    int lane = threadIdx.x & 31, w = threadIdx.x >> 5;
    int n = blockIdx.x * 8 + w;
    float dn = g_denom[n] + 1e-16f;
    bool act1 = lane < 8;
    int c0 = lane;
    int c1 = act1 ? lane + 32 : 0;
    float v0 = g_acc2[n * NCLASS + c0] / dn + b2[c0];
    float v1 = g_acc2[n * NCLASS + c1] / dn + b2[c1];
    float vm = act1 ? fmaxf(v0, v1) : v0;
    #pragma unroll
    for (int o = 16; o > 0; o >>= 1)
        vm = fmaxf(vm, __shfl_xor_sync(0xffffffffu, vm, o));
    float s = expf(v0 - vm) + (act1 ? expf(v1 - vm) : 0.f);
    #pragma unroll
    for (int o = 16; o > 0; o >>= 1)
        s += __shfl_xor_sync(0xffffffffu, s, o);
    float lse = vm + logf(s);
    out[n * NCLASS + c0] = v0 - lse;
    if (act1) out[n * NCLASS + 32 + lane] = v1 - lse;
}

// ---------------- launch ----------------------------------------------------
extern "C" void kernel_launch(void* const* d_in, const int* in_sizes, int n_in,
                              void* d_out, int out_size) {
    const float* x   = (const float*)d_in[0];
    const int*   ei  = (const int*)d_in[1];
    const float* W1  = (const float*)d_in[2];
    const float* as1 = (const float*)d_in[3];
    const float* ad1 = (const float*)d_in[4];
    const float* b1  = (const float*)d_in[5];
    const float* W2  = (const float*)d_in[6];
    const float* as2 = (const float*)d_in[7];
    const float* ad2 = (const float*)d_in[8];
    const float* b2  = (const float*)d_in[9];
    const int* src = ei;
    const int* dst = ei + N_EDGES;
    float* out = (float*)d_out;

    const int TPB = 256;
    int init1_grid = (N_NODES * NHID + TPB - 1) / TPB;
    int init2_grid = (N_NODES * NCLASS + TPB - 1) / TPB;
    int emax_grid  = (N_EDGES + TPB - 1) / TPB;
    int eacc_grid  = (N_EDGES * 32 + TPB - 1) / TPB;

    // ---- layer 1 ----
    init_kernel<<<init1_grid, TPB>>>(N_NODES * NHID, 0);
    gemm1_kernel<<<N_NODES / 32, TPB>>>(x, W1, as1, ad1);
    edge_max_kernel<<<emax_grid, TPB>>>(src, dst);
    edge_accum_kernel<NHID><<<eacc_grid, TPB>>>(src, dst);
    finalize1_kernel<<<init1_grid, TPB>>>(b1);

    // ---- layer 2 ----
    init_kernel<<<init2_grid, TPB>>>(N_NODES * NCLASS, 1);
    gemm2_kernel<<<N_NODES / 8, TPB>>>(W2, as2, ad2);
    edge_max_kernel<<<emax_grid, TPB>>>(src, dst);
    edge_accum_kernel<NCLASS><<<eacc_grid, TPB>>>(src, dst);
    finalize2_kernel<<<N_NODES / 8, TPB>>>(b2, out);
}

// round 2
// speedup vs baseline: 1.5871x; 1.5871x over previous
#include <cuda_runtime.h>
#include <cuda_bf16.h>
#include <math.h>
#include <limits.h>

#define N_NODES 100000
#define N_EDGES 1600000
#define NFEAT 128
#define NHID 32
#define NCLASS 40
#define NEG_SLOPE 0.2f

// ---------------- scratch (device globals; 16B-aligned for v4 atomics) -----
__device__ __align__(16) float g_h1[N_NODES * NHID];
__device__ __align__(16) float g_acc1[N_NODES * NHID];
__device__ __align__(16) float g_x2[N_NODES * NHID];
__device__ __align__(16) float g_h2[N_NODES * NCLASS];
__device__ __align__(16) float g_acc2[N_NODES * NCLASS];
__device__ float g_asrc[N_NODES];
__device__ float g_adst[N_NODES];
__device__ float g_denom[N_NODES];
__device__ int   g_mord[N_NODES];

// ---------------- helpers ---------------------------------------------------
__device__ __forceinline__ int f2ord(float f) {
    int i = __float_as_int(f);
    return i >= 0 ? i : (i ^ 0x7FFFFFFF);
}
__device__ __forceinline__ float ord2f(int i) {
    return __int_as_float(i >= 0 ? i : (i ^ 0x7FFFFFFF));
}
__device__ __forceinline__ float lrelu(float x) {
    return x > 0.f ? x : NEG_SLOPE * x;
}
__device__ __forceinline__ void red_add_v4(float* p, float4 v) {
    asm volatile("red.global.add.v4.f32 [%0], {%1,%2,%3,%4};"
                 :: "l"(p), "f"(v.x), "f"(v.y), "f"(v.z), "f"(v.w) : "memory");
}
__device__ __forceinline__ void red_add_f32(float* p, float v) {
    asm volatile("red.global.add.f32 [%0], %1;" :: "l"(p), "f"(v) : "memory");
}

// ---------------- init ------------------------------------------------------
__global__ void init_kernel(int accN, int layer) {
    int i = blockIdx.x * blockDim.x + threadIdx.x;
    if (i < accN) {
        if (layer == 0) g_acc1[i] = 0.f;
        else            g_acc2[i] = 0.f;
    }
    if (i < N_NODES) {
        g_denom[i] = 0.f;
        g_mord[i]  = INT_MIN;
    }
}

// ---------------- layer 1 GEMM: h1 = x @ W1, + alpha_src/dst ---------------
__global__ void gemm1_kernel(const float* __restrict__ x,
                             const float* __restrict__ W1,
                             const float* __restrict__ a_src,
                             const float* __restrict__ a_dst) {
    __shared__ float Wsh[NFEAT * NHID];
    __shared__ float xsh[32][NFEAT];
    __shared__ float as[NHID], ad[NHID];
    int tid = threadIdx.x;
    int base = blockIdx.x * 32;

    for (int i = tid; i < NFEAT * NHID; i += 256) Wsh[i] = W1[i];
    if (tid < NHID) { as[tid] = a_src[tid]; ad[tid] = a_dst[tid]; }
    for (int i = tid; i < 32 * NFEAT; i += 256) {
        int r = i >> 7, cc = i & 127;
        xsh[r][cc] = x[(size_t)(base + r) * NFEAT + cc];
    }
    __syncthreads();

    int c = tid & 31, rr = tid >> 5;
    float acc[4] = {0.f, 0.f, 0.f, 0.f};
    #pragma unroll 8
    for (int k = 0; k < NFEAT; k++) {
        float wk = Wsh[k * NHID + c];
        acc[0] += xsh[rr     ][k] * wk;
        acc[1] += xsh[rr +  8][k] * wk;
        acc[2] += xsh[rr + 16][k] * wk;
        acc[3] += xsh[rr + 24][k] * wk;
    }
    #pragma unroll
    for (int j = 0; j < 4; j++) {
        int n = base + rr + 8 * j;
        g_h1[n * NHID + c] = acc[j];
        float av = acc[j] * as[c];
        float dv = acc[j] * ad[c];
        #pragma unroll
        for (int o = 16; o > 0; o >>= 1) {
            av += __shfl_xor_sync(0xffffffffu, av, o);
            dv += __shfl_xor_sync(0xffffffffu, dv, o);
        }
        if (c == 0) { g_asrc[n] = av; g_adst[n] = dv; }
    }
}

// ---------------- layer 2 GEMM ---------------------------------------------
__global__ void gemm2_kernel(const float* __restrict__ W2,
                             const float* __restrict__ a_src,
                             const float* __restrict__ a_dst) {
    __shared__ float Wsh[NHID * NCLASS];
    __shared__ float as[NCLASS], ad[NCLASS];
    int tid = threadIdx.x;
    for (int i = tid; i < NHID * NCLASS; i += 256) Wsh[i] = W2[i];
    if (tid < NCLASS) { as[tid] = a_src[tid]; ad[tid] = a_dst[tid]; }
    __syncthreads();

    int lane = tid & 31, w = tid >> 5;
    int n = blockIdx.x * 8 + w;
    float hval = g_x2[n * NHID + lane];
    bool act1 = lane < 8;
    int c0 = lane;
    int c1 = act1 ? lane + 32 : 0;
    float acc0 = 0.f, acc1 = 0.f;
    #pragma unroll
    for (int k = 0; k < NHID; k++) {
        float hk = __shfl_sync(0xffffffffu, hval, k);
        acc0 += hk * Wsh[k * NCLASS + c0];
        acc1 += hk * Wsh[k * NCLASS + c1];
    }
    g_h2[n * NCLASS + c0] = acc0;
    if (act1) g_h2[n * NCLASS + 32 + lane] = acc1;

    float av = acc0 * as[c0] + (act1 ? acc1 * as[c1] : 0.f);
    float dv = acc0 * ad[c0] + (act1 ? acc1 * ad[c1] : 0.f);
    #pragma unroll
    for (int o = 16; o > 0; o >>= 1) {
        av += __shfl_xor_sync(0xffffffffu, av, o);
        dv += __shfl_xor_sync(0xffffffffu, dv, o);
    }
    if (lane == 0) { g_asrc[n] = av; g_adst[n] = dv; }
}

// ---------------- edge pass 1: segment max ---------------------------------
__global__ void edge_max_kernel(const int* __restrict__ src,
                                const int* __restrict__ dst) {
    int e = blockIdx.x * blockDim.x + threadIdx.x;
    if (e >= N_EDGES) return;
    int s = src[e], d = dst[e];
    float sc = lrelu(g_asrc[s] + g_adst[d]);
    atomicMax(&g_mord[d], f2ord(sc));
}

// ---------------- edge pass 2: fused exp + denom + v4 scatter --------------
// Flat mapping: one thread per float4 chunk. VPE = C/4 threads per edge.
template <int C>
__global__ void edge_accum_kernel(const int* __restrict__ src,
                                  const int* __restrict__ dst) {
    constexpr int VPE = C / 4;  // 8 (C=32) or 10 (C=40)
    int t = blockIdx.x * blockDim.x + threadIdx.x;
    int e = t / VPE;
    int v = t - e * VPE;
    if (e >= N_EDGES) return;
    const float* __restrict__ h  = (C == NHID) ? g_h1  : g_h2;
    float* __restrict__       ac = (C == NHID) ? g_acc1 : g_acc2;
    int s = __ldg(&src[e]), d = __ldg(&dst[e]);
    float sc = lrelu(g_asrc[s] + g_adst[d]);
    float ee = __expf(sc - ord2f(g_mord[d]));
    if (v == 0) red_add_f32(&g_denom[d], ee);
    float4 hv = __ldg(reinterpret_cast<const float4*>(h + (size_t)s * C) + v);
    hv.x *= ee; hv.y *= ee; hv.z *= ee; hv.w *= ee;
    red_add_v4(ac + (size_t)d * C + 4 * v, hv);
}

// ---------------- finalize layer 1 -----------------------------------------
__global__ void finalize1_kernel(const float* __restrict__ b1) {
    int i = blockIdx.x * blockDim.x + threadIdx.x;
    if (i >= N_NODES * NHID) return;
    int n = i >> 5, c = i & 31;
    float v = g_acc1[i] / (g_denom[n] + 1e-16f) + b1[c];
    g_x2[i] = v > 0.f ? v : 0.f;
}

// ---------------- finalize layer 2: log_softmax ----------------------------
__global__ void finalize2_kernel(const float* __restrict__ b2,
                                 float* __restrict__ out) {
    int lane = threadIdx.x & 31, w = threadIdx.x >> 5;
    int n = blockIdx.x * 8 + w;
    float dn = g_denom[n] + 1e-16f;
    bool act1 = lane < 8;
    int c0 = lane;
    int c1 = act1 ? lane + 32 : 0;
    float v0 = g_acc2[n * NCLASS + c0] / dn + b2[c0];
    float v1 = g_acc2[n * NCLASS + c1] / dn + b2[c1];
    float vm = act1 ? fmaxf(v0, v1) : v0;
    #pragma unroll
    for (int o = 16; o > 0; o >>= 1)
        vm = fmaxf(vm, __shfl_xor_sync(0xffffffffu, vm, o));
    float s = expf(v0 - vm) + (act1 ? expf(v1 - vm) : 0.f);
    #pragma unroll
    for (int o = 16; o > 0; o >>= 1)
        s += __shfl_xor_sync(0xffffffffu, s, o);
    float lse = vm + logf(s);
    out[n * NCLASS + c0] = v0 - lse;
    if (act1) out[n * NCLASS + 32 + lane] = v1 - lse;
}

// ---------------- launch ----------------------------------------------------
extern "C" void kernel_launch(void* const* d_in, const int* in_sizes, int n_in,
                              void* d_out, int out_size) {
    const float* x   = (const float*)d_in[0];
    const int*   ei  = (const int*)d_in[1];
    const float* W1  = (const float*)d_in[2];
    const float* as1 = (const float*)d_in[3];
    const float* ad1 = (const float*)d_in[4];
    const float* b1  = (const float*)d_in[5];
    const float* W2  = (const float*)d_in[6];
    const float* as2 = (const float*)d_in[7];
    const float* ad2 = (const float*)d_in[8];
    const float* b2  = (const float*)d_in[9];
    const int* src = ei;
    const int* dst = ei + N_EDGES;
    float* out = (float*)d_out;

    const int TPB = 256;
    int init1_grid = (N_NODES * NHID + TPB - 1) / TPB;
    int init2_grid = (N_NODES * NCLASS + TPB - 1) / TPB;
    int emax_grid  = (N_EDGES + TPB - 1) / TPB;
    int eacc1_grid = (N_EDGES * (NHID / 4) + TPB - 1) / TPB;
    int eacc2_grid = (N_EDGES * (NCLASS / 4) + TPB - 1) / TPB;

    // ---- layer 1 ----
    init_kernel<<<init1_grid, TPB>>>(N_NODES * NHID, 0);
    gemm1_kernel<<<N_NODES / 32, TPB>>>(x, W1, as1, ad1);
    edge_max_kernel<<<emax_grid, TPB>>>(src, dst);
    edge_accum_kernel<NHID><<<eacc1_grid, TPB>>>(src, dst);
    finalize1_kernel<<<init1_grid, TPB>>>(b1);

    // ---- layer 2 ----
    init_kernel<<<init2_grid, TPB>>>(N_NODES * NCLASS, 1);
    gemm2_kernel<<<N_NODES / 8, TPB>>>(W2, as2, ad2);
    edge_max_kernel<<<emax_grid, TPB>>>(src, dst);
    edge_accum_kernel<NCLASS><<<eacc2_grid, TPB>>>(src, dst);
    finalize2_kernel<<<N_NODES / 8, TPB>>>(b2, out);
}